// round 1
// baseline (speedup 1.0000x reference)
#include <cuda_runtime.h>

typedef unsigned long long u64;

// ---------------- packed fp32x2 helpers (Blackwell FFMA2 path) ----------------
__device__ __forceinline__ u64 pack_dup(float a) {
    u64 r; asm("mov.b64 %0, {%1, %1};" : "=l"(r) : "f"(a)); return r;
}
__device__ __forceinline__ void fma2(u64& c, u64 a, u64 b) {
    asm("fma.rn.f32x2 %0, %1, %2, %0;" : "+l"(c) : "l"(a), "l"(b));
}
__device__ __forceinline__ float2 unpack2(u64 v) {
    float lo, hi; asm("mov.b64 {%0, %1}, %2;" : "=f"(lo), "=f"(hi) : "l"(v));
    return make_float2(lo, hi);
}

// ---------------- problem constants ----------------
#define NB   8          // nodes per CTA
#define MCO  9          // (LMAX+1)^2 spherical coeffs
#define AA   42         // S2 grid points
#define CH   128        // C == H == 128
#define XW   1152       // M*C flat width

// ---------------- shared memory layout (floats) ----------------
#define S_G    0                    // 8*42*128 = 43008   (h in rows 0..71, then g/gg, then final out)
#define S_B1   43008                // 72*128   = 9216    (h1, then h2)
#define S_PAN  52224                // 16*256   = 4096    (weight k-panel)
#define S_TG   56320                // 378  to_grid [A,M]
#define S_FG   (S_TG + 378)         // 378  from_grid [M,A]
#define S_GB   (S_FG + 378)         // 256  grid_b
#define S_BB1  (S_GB + 256)         // 128  b1
#define S_BB2  (S_BB1 + 128)        // 128  b2
#define S_NW   (S_BB2 + 128)        // 384  norm_weight [3,128]
#define SMEM_FLOATS (S_NW + 384)    // 57972 floats = 231888 bytes (<= 232448)

// Per-degree dense 128x128 GEMM over rows ordered r = m*8 + i, grouped by degree l.
// Out[row][col] = sum_k B[l(row)][col][k] * A[row][k]   (+ bias0 on l=0 rows)
// B panel [16k x 128col] staged in s_pan with register prefetch.
__device__ __forceinline__ void gemm_degree(const float* __restrict__ A,
                                            const float* __restrict__ W,
                                            float* __restrict__ O,
                                            const float* __restrict__ bias0,
                                            float* __restrict__ s_pan)
{
    const int tid = threadIdx.x;
    const int cg  = tid & 31;     // col group: cols cg*4..cg*4+3
    const int rg  = tid >> 5;     // row group: rows rg + 8*j
    const int hh  = tid >> 1;     // panel-load row (0..127)
    const int kb  = (tid & 1) * 2;

    const float4* wg = (const float4*)W;
    float4 pfa = wg[hh * 32 + kb];        // tile 0 (l=0, kt=0)
    float4 pfb = wg[hh * 32 + kb + 1];

#pragma unroll
    for (int l = 0; l < 3; l++) {
        const int TR   = 2 * l + 1;
        const int base = l * l * 8;
        const float* Ar[5];
#pragma unroll
        for (int j = 0; j < 5; j++) {
            int jj = (j < TR) ? j : 0;
            Ar[j] = A + (base + rg + 8 * jj) * 128;
        }
        u64 a0[5], a1[5];
#pragma unroll
        for (int j = 0; j < 5; j++) { a0[j] = 0ull; a1[j] = 0ull; }

        for (int kt = 0; kt < 8; kt++) {
            __syncthreads();
            s_pan[(kb * 4 + 0) * 128 + hh] = pfa.x;
            s_pan[(kb * 4 + 1) * 128 + hh] = pfa.y;
            s_pan[(kb * 4 + 2) * 128 + hh] = pfa.z;
            s_pan[(kb * 4 + 3) * 128 + hh] = pfa.w;
            s_pan[((kb + 1) * 4 + 0) * 128 + hh] = pfb.x;
            s_pan[((kb + 1) * 4 + 1) * 128 + hh] = pfb.y;
            s_pan[((kb + 1) * 4 + 2) * 128 + hh] = pfb.z;
            s_pan[((kb + 1) * 4 + 3) * 128 + hh] = pfb.w;
            __syncthreads();

            {   // prefetch next tile (linear over l,kt)
                int t = l * 8 + kt + 1;
                if (t < 24) {
                    int ll = t >> 3, ktt = t & 7;
                    const float4* wn = (const float4*)(W + ll * 16384);
                    pfa = wn[hh * 32 + ktt * 4 + kb];
                    pfb = wn[hh * 32 + ktt * 4 + kb + 1];
                }
            }

            const int k0 = kt * 16;
#pragma unroll
            for (int kk = 0; kk < 16; kk++) {
                ulonglong2 wv = ((const ulonglong2*)s_pan)[kk * 32 + cg];
#pragma unroll
                for (int j = 0; j < TR; j++) {
                    u64 av = pack_dup(Ar[j][k0 + kk]);
                    fma2(a0[j], av, wv.x);
                    fma2(a1[j], av, wv.y);
                }
            }
        }
        // epilogue
#pragma unroll
        for (int j = 0; j < TR; j++) {
            float2 lo = unpack2(a0[j]);
            float2 hi = unpack2(a1[j]);
            float4 o4 = make_float4(lo.x, lo.y, hi.x, hi.y);
            if (l == 0) {
                o4.x += bias0[cg * 4 + 0];
                o4.y += bias0[cg * 4 + 1];
                o4.z += bias0[cg * 4 + 2];
                o4.w += bias0[cg * 4 + 3];
            }
            ((float4*)O)[(base + rg + 8 * j) * 32 + cg] = o4;
        }
    }
}

extern "C" __global__ void __launch_bounds__(256, 1)
eqffn_kernel(const float* __restrict__ x,
             const float* __restrict__ nwg,
             const float* __restrict__ w1g,
             const float* __restrict__ b1g,
             const float* __restrict__ gwg,
             const float* __restrict__ gbg,
             const float* __restrict__ w2g,
             const float* __restrict__ b2g,
             const float* __restrict__ tgg,
             const float* __restrict__ fgg,
             float* __restrict__ y,
             int N)
{
    extern __shared__ float sm[];
    float* s_g   = sm + S_G;
    float* s_h1  = sm + S_B1;
    float* s_pan = sm + S_PAN;
    float* s_tg  = sm + S_TG;
    float* s_fg  = sm + S_FG;
    float* s_gb  = sm + S_GB;
    float* s_bb1 = sm + S_BB1;
    float* s_bb2 = sm + S_BB2;
    float* s_nw  = sm + S_NW;

    const int tid  = threadIdx.x;
    const int lane = tid & 31;
    const int wrp  = tid >> 5;   // node-within-block for vector phases
    const int cg   = lane;
    const int rg   = wrp;

    // small constants -> smem
    for (int i = tid; i < 378; i += 256) s_tg[i] = tgg[i];
    for (int i = tid; i < 378; i += 256) s_fg[i] = fgg[i];
    if (tid < 256) s_gb[tid] = gbg[tid];
    if (tid < 128) { s_bb1[tid] = b1g[tid]; s_bb2[tid] = b2g[tid]; }
    for (int i = tid; i < 384; i += 256) s_nw[i] = nwg[i];

    const int node = blockIdx.x * NB + wrp;
    const bool valid = node < N;

    // ---------- Phase 0: load x, sumsq, pack + RMS-norm into s_g rows (m*8+i) ----------
    float v[36];
    float ss = 0.f;
    if (valid) {
        const float* xr = x + (size_t)node * XW;
#pragma unroll
        for (int k = 0; k < 36; k++) { v[k] = xr[lane + 32 * k]; ss += v[k] * v[k]; }
    } else {
#pragma unroll
        for (int k = 0; k < 36; k++) v[k] = 0.f;
    }
#pragma unroll
    for (int o = 16; o; o >>= 1) ss += __shfl_xor_sync(0xffffffffu, ss, o);
    const float rinv = rsqrtf(ss * (1.0f / 1152.0f) + 1e-6f);

    __syncthreads();   // s_nw ready
#pragma unroll
    for (int k = 0; k < 36; k++) {
        int j = lane + 32 * k;
        int l, coeff, c;
        if (j < 128)      { l = 0; coeff = 0; c = j; }
        else if (j < 512) { l = 1; int q = j - 128; c = q / 3; coeff = 1 + (q - 3 * c); }
        else              { l = 2; int q = j - 512; c = q / 5; coeff = 4 + (q - 5 * c); }
        s_g[(coeff * NB + wrp) * 128 + c] = v[k] * rinv * s_nw[l * 128 + c];
    }
    __syncthreads();

    // ---------- Phase 1: GEMM1  h1[m,i][h] = sum_c w1[l][h][c] * h[m,i][c]  (+b1 on m=0) ----------
    gemm_degree(s_g, w1g, s_h1, s_bb1, s_pan);
    __syncthreads();

    // ---------- Phase 2: to_grid  g[i,a][h] = sum_m tg[a][m] * h1[m,i][h] ----------
    {
        float4 h1r[9];
#pragma unroll
        for (int m = 0; m < MCO; m++)
            h1r[m] = ((const float4*)s_h1)[(m * NB + wrp) * 32 + lane];
        for (int a = 0; a < AA; a++) {
            float4 acc = make_float4(0.f, 0.f, 0.f, 0.f);
#pragma unroll
            for (int m = 0; m < MCO; m++) {
                float t = s_tg[a * MCO + m];
                acc.x += t * h1r[m].x; acc.y += t * h1r[m].y;
                acc.z += t * h1r[m].z; acc.w += t * h1r[m].w;
            }
            ((float4*)s_g)[(wrp * AA + a) * 32 + lane] = acc;
        }
    }
    __syncthreads();

    // ---------- Phase 3+4: GEMM2 (336 rows x 256 cols x 128 k) + SwiGLU, gg overwrites g ----------
    {
        const float4* wg4 = (const float4*)gwg;
        float4 p0 = wg4[tid * 32 + 0];
        float4 p1 = wg4[tid * 32 + 1];
        float4 p2 = wg4[tid * 32 + 2];
        float4 p3 = wg4[tid * 32 + 3];

        const float gb0 = s_gb[cg * 4 + 0], gb1 = s_gb[cg * 4 + 1];
        const float gb2 = s_gb[cg * 4 + 2], gb3 = s_gb[cg * 4 + 3];
        const float hb0 = s_gb[128 + cg * 4 + 0], hb1 = s_gb[128 + cg * 4 + 1];
        const float hb2 = s_gb[128 + cg * 4 + 2], hb3 = s_gb[128 + cg * 4 + 3];

        for (int ch = 0; ch < 7; ch++) {
            const int rbase = ch * 48;
            const float* gr[6];
#pragma unroll
            for (int j = 0; j < 6; j++) gr[j] = s_g + (rbase + rg + 8 * j) * 128;

            u64 aL0[6], aL1[6], aH0[6], aH1[6];
#pragma unroll
            for (int j = 0; j < 6; j++) { aL0[j] = 0ull; aL1[j] = 0ull; aH0[j] = 0ull; aH1[j] = 0ull; }

            for (int kt = 0; kt < 8; kt++) {
                __syncthreads();
                s_pan[ 0 * 256 + tid] = p0.x; s_pan[ 1 * 256 + tid] = p0.y;
                s_pan[ 2 * 256 + tid] = p0.z; s_pan[ 3 * 256 + tid] = p0.w;
                s_pan[ 4 * 256 + tid] = p1.x; s_pan[ 5 * 256 + tid] = p1.y;
                s_pan[ 6 * 256 + tid] = p1.z; s_pan[ 7 * 256 + tid] = p1.w;
                s_pan[ 8 * 256 + tid] = p2.x; s_pan[ 9 * 256 + tid] = p2.y;
                s_pan[10 * 256 + tid] = p2.z; s_pan[11 * 256 + tid] = p2.w;
                s_pan[12 * 256 + tid] = p3.x; s_pan[13 * 256 + tid] = p3.y;
                s_pan[14 * 256 + tid] = p3.z; s_pan[15 * 256 + tid] = p3.w;
                __syncthreads();

                if (!(ch == 6 && kt == 7)) {
                    int nkt = (kt + 1) & 7;
                    p0 = wg4[tid * 32 + nkt * 4 + 0];
                    p1 = wg4[tid * 32 + nkt * 4 + 1];
                    p2 = wg4[tid * 32 + nkt * 4 + 2];
                    p3 = wg4[tid * 32 + nkt * 4 + 3];
                }

                const int k0 = kt * 16;
#pragma unroll
                for (int kk = 0; kk < 16; kk++) {
                    ulonglong2 wlo = ((const ulonglong2*)s_pan)[kk * 64 + cg];
                    ulonglong2 whi = ((const ulonglong2*)s_pan)[kk * 64 + 32 + cg];
#pragma unroll
                    for (int j = 0; j < 6; j++) {
                        u64 g2 = pack_dup(gr[j][k0 + kk]);
                        fma2(aL0[j], g2, wlo.x);
                        fma2(aL1[j], g2, wlo.y);
                        fma2(aH0[j], g2, whi.x);
                        fma2(aH1[j], g2, whi.y);
                    }
                }
            }
            __syncwarp();   // rows of this chunk are owned by this warp only
            // SwiGLU epilogue, write gg in place
#pragma unroll
            for (int j = 0; j < 6; j++) {
                float2 l01 = unpack2(aL0[j]), l23 = unpack2(aL1[j]);
                float2 h01 = unpack2(aH0[j]), h23 = unpack2(aH1[j]);
                float z0 = l01.x + gb0, z1 = l01.y + gb1, z2 = l23.x + gb2, z3 = l23.y + gb3;
                float g0 = h01.x + hb0, g1 = h01.y + hb1, g2v = h23.x + hb2, g3 = h23.y + hb3;
                float4 o4;
                o4.x = z0 * (1.f / (1.f + __expf(-z0))) * g0;
                o4.y = z1 * (1.f / (1.f + __expf(-z1))) * g1;
                o4.z = z2 * (1.f / (1.f + __expf(-z2))) * g2v;
                o4.w = z3 * (1.f / (1.f + __expf(-z3))) * g3;
                ((float4*)s_g)[(rbase + rg + 8 * j) * 32 + cg] = o4;
            }
        }
    }
    __syncthreads();

    // ---------- Phase 5: from_grid  h2[m,i][h] = sum_a fg[m][a] * gg[i,a][h] ----------
    {
        float4 acc[9];
#pragma unroll
        for (int m = 0; m < MCO; m++) acc[m] = make_float4(0.f, 0.f, 0.f, 0.f);
        for (int a = 0; a < AA; a++) {
            float4 g4 = ((const float4*)s_g)[(wrp * AA + a) * 32 + lane];
#pragma unroll
            for (int m = 0; m < MCO; m++) {
                float f = s_fg[m * AA + a];
                acc[m].x += f * g4.x; acc[m].y += f * g4.y;
                acc[m].z += f * g4.z; acc[m].w += f * g4.w;
            }
        }
#pragma unroll
        for (int m = 0; m < MCO; m++)
            ((float4*)s_h1)[(m * NB + wrp) * 32 + lane] = acc[m];
    }
    __syncthreads();

    // ---------- Phase 6: GEMM3  out[m,i][c] = sum_h w2[l][c][h] * h2[m,i][h]  (+b2 on m=0) ----------
    gemm_degree(s_h1, w2g, s_g, s_bb2, s_pan);
    __syncthreads();

    // ---------- Phase 7: unpack + store ----------
    if (valid) {
        float* yr = y + (size_t)node * XW;
#pragma unroll
        for (int k = 0; k < 36; k++) {
            int j = lane + 32 * k;
            int coeff, c;
            if (j < 128)      { coeff = 0; c = j; }
            else if (j < 512) { int q = j - 128; c = q / 3; coeff = 1 + (q - 3 * c); }
            else              { int q = j - 512; c = q / 5; coeff = 4 + (q - 5 * c); }
            yr[j] = s_g[(coeff * NB + wrp) * 128 + c];
        }
    }
}

extern "C" void kernel_launch(void* const* d_in, const int* in_sizes, int n_in,
                              void* d_out, int out_size)
{
    const float* x   = (const float*)d_in[0];
    const float* nw  = (const float*)d_in[1];
    const float* w1  = (const float*)d_in[2];
    const float* b1  = (const float*)d_in[3];
    const float* gw  = (const float*)d_in[4];
    const float* gb  = (const float*)d_in[5];
    const float* w2  = (const float*)d_in[6];
    const float* b2  = (const float*)d_in[7];
    const float* tg  = (const float*)d_in[8];
    const float* fg  = (const float*)d_in[9];
    float* y = (float*)d_out;

    const int N = in_sizes[0] / XW;
    const int smem_bytes = SMEM_FLOATS * 4;
    cudaFuncSetAttribute(eqffn_kernel, cudaFuncAttributeMaxDynamicSharedMemorySize, smem_bytes);
    const int grid = (N + NB - 1) / NB;
    eqffn_kernel<<<grid, 256, smem_bytes>>>(x, nw, w1, b1, gw, gb, w2, b2, tg, fg, y, N);
}